// round 5
// baseline (speedup 1.0000x reference)
#include <cuda_runtime.h>

// Problem dims
#define NB 256
#define NT 128
#define NS 12
#define NC 4
#define NM 6
#define MU_C 0.1f

// Output layout: flattened tuple (ku, Ku, ks, Ks, dV, opterr, Vx, Vxx), float32
#define O_ku   0
#define O_Ku   131072
#define O_ks   1703936
#define O_Ks   1900544
#define O_dV   4259840
#define O_opt  4260352
#define O_Vx   4260353
#define O_Vxx  4263425

// Stage (per-(b,t) input block) layout inside shared memory, in floats
#define SG_FXX 0       // 1728
#define SG_FXU 1728    // 576
#define SG_FUU 2304    // 192
#define SG_FX  2496    // 144
#define SG_QXX 2640    // 144
#define SG_FU  2784    // 48
#define SG_QXU 2832    // 48
#define SG_CX  2880    // 72
#define SG_CU  2952    // 24
#define SG_QUU 2976    // 16
#define SG_QX  2992    // 12
#define SG_QU  3004    // 4
#define SG_C   3008    // 6
#define SG_S   3014    // 6
#define SG_TOT 3020

__device__ __forceinline__ void cpa16(float* dst, const void* src) {
    unsigned ds = (unsigned)__cvta_generic_to_shared(dst);
    asm volatile("cp.async.ca.shared.global [%0], [%1], 16;" :: "r"(ds), "l"(src));
}
__device__ __forceinline__ void cpa4(float* dst, const void* src) {
    unsigned ds = (unsigned)__cvta_generic_to_shared(dst);
    asm volatile("cp.async.ca.shared.global [%0], [%1], 4;" :: "r"(ds), "l"(src));
}
__device__ __forceinline__ void cpa_commit() {
    asm volatile("cp.async.commit_group;");
}
__device__ __forceinline__ void cpa_wait_all() {
    asm volatile("cp.async.wait_group 0;");
}

__global__ void init_opt_kernel(float* out) { out[O_opt] = 0.0f; }

__global__ void __launch_bounds__(128, 2) ddp_backward_kernel(
    const float* __restrict__ g_qx,  const float* __restrict__ g_qu,
    const float* __restrict__ g_qxx, const float* __restrict__ g_qxu,
    const float* __restrict__ g_quu, const float* __restrict__ g_fx,
    const float* __restrict__ g_fu,  const float* __restrict__ g_fxx,
    const float* __restrict__ g_fxu, const float* __restrict__ g_fuu,
    const float* __restrict__ g_cx,  const float* __restrict__ g_cu,
    const float* __restrict__ g_c,   const float* __restrict__ g_s,
    const float* __restrict__ g_px,  const float* __restrict__ g_pxx,
    float* __restrict__ out)
{
    const float REG_FAC = (float)(1.6 * 1.6 - 1.0);   // REG_BASE**REG - 1

    __shared__ float stg[2][SG_TOT];
    __shared__ float sVx[NS], sVxx[NS * NS];
    // phase-1 workspace
    __shared__ float fxV[144], Wxx[144], fuV[48], Wxu[48], Wuu[16];
    __shared__ float QxB[12], QuB[4];
    __shared__ float sc_[6], r_[6], cinv_[6], cinr_[6];
    // phase-2 workspace
    __shared__ float Qxx2[144], tQux[48], Quu2[16], Amat[16], Qx2[12], Quh[4];
    // solver workspace
    __shared__ float LUm[16], rdg[4];
    __shared__ int   perm[4];
    __shared__ float kK[4 * 13];
    // phase-4 workspace
    __shared__ float QxuKu[144], KtQ[48], VxT[12];
    __shared__ float sdv0, sdv1, serrq, serrm;

    const int b   = blockIdx.x;
    const int tid = threadIdx.x;

    // ---- issue cp.async prefetch of one (b,t) stage into stg[bsel] ----
    auto issue_stage = [&](int bsel, int off) {
        float* d = stg[bsel];
        {
            const float4* s = (const float4*)(g_fxx + (size_t)off * 1728);
            for (int i = tid; i < 432; i += 128) cpa16(d + SG_FXX + 4 * i, s + i);
        }
        {
            const float4* s = (const float4*)(g_fxu + (size_t)off * 576);
            for (int i = tid; i < 144; i += 128) cpa16(d + SG_FXU + 4 * i, s + i);
        }
        {
            const float4* s = (const float4*)(g_fuu + (size_t)off * 192);
            if (tid < 48) cpa16(d + SG_FUU + 4 * tid, s + tid);
        }
        {
            const float4* s = (const float4*)(g_fx + (size_t)off * 144);
            if (tid >= 48 && tid < 84) cpa16(d + SG_FX + 4 * (tid - 48), s + (tid - 48));
        }
        {
            const float4* s = (const float4*)(g_qxx + (size_t)off * 144);
            if (tid >= 84 && tid < 120) cpa16(d + SG_QXX + 4 * (tid - 84), s + (tid - 84));
        }
        {
            const float4* s = (const float4*)(g_fu + (size_t)off * 48);
            if (tid < 12) cpa16(d + SG_FU + 4 * tid, s + tid);
        }
        {
            const float4* s = (const float4*)(g_qxu + (size_t)off * 48);
            if (tid >= 12 && tid < 24) cpa16(d + SG_QXU + 4 * (tid - 12), s + (tid - 12));
        }
        {
            const float4* s = (const float4*)(g_cx + (size_t)off * 72);
            if (tid >= 24 && tid < 42) cpa16(d + SG_CX + 4 * (tid - 24), s + (tid - 24));
        }
        {
            const float4* s = (const float4*)(g_cu + (size_t)off * 24);
            if (tid >= 42 && tid < 48) cpa16(d + SG_CU + 4 * (tid - 42), s + (tid - 42));
        }
        {
            const float4* s = (const float4*)(g_quu + (size_t)off * 16);
            if (tid >= 120 && tid < 124) cpa16(d + SG_QUU + 4 * (tid - 120), s + (tid - 120));
        }
        {
            const float4* s = (const float4*)(g_qx + (size_t)off * 12);
            if (tid >= 124 && tid < 127) cpa16(d + SG_QX + 4 * (tid - 124), s + (tid - 124));
        }
        {
            const float4* s = (const float4*)(g_qu + (size_t)off * 4);
            if (tid == 127) cpa16(d + SG_QU, s);
        }
        if (tid >= 96 && tid < 102) cpa4(d + SG_C + (tid - 96), g_c + (size_t)off * 6 + (tid - 96));
        if (tid >= 102 && tid < 108) cpa4(d + SG_S + (tid - 102), g_s + (size_t)off * 6 + (tid - 102));
        cpa_commit();
    };

    // ---- prologue: prefetch step T-1, init carry ----
    issue_stage(0, b * NT + (NT - 1));
    if (tid < NS) sVx[tid] = g_px[b * NS + tid];
    for (int e = tid; e < 144; e += 128) sVxx[e] = g_pxx[b * 144 + e];
    if (tid == 0) { sdv0 = 0.0f; sdv1 = 0.0f; serrq = 0.0f; serrm = 0.0f; }

    int buf = 0;
    for (int t = NT - 1; t >= 0; --t) {
        cpa_wait_all();
        __syncthreads();                    // S0: stage ready + previous P5 done

        if (t > 0) issue_stage(buf ^ 1, b * NT + (t - 1));   // overlap next load

        const float* S   = stg[buf];
        const float* Fxx = S + SG_FXX;
        const float* Fxu = S + SG_FXU;
        const float* Fuu = S + SG_FUU;
        const float* Fx  = S + SG_FX;
        const float* Qxi2= S + SG_QXX;
        const float* Fu  = S + SG_FU;
        const float* Qxui= S + SG_QXU;
        const float* Cx  = S + SG_CX;
        const float* Cu  = S + SG_CU;
        const float* Quui= S + SG_QUU;
        const float* Qxi = S + SG_QX;
        const float* Qui = S + SG_QU;
        const float* Cc  = S + SG_C;
        const float* Ssv = S + SG_S;

        // ================= Phase 1 (needs only carry + inputs) =================
        if (tid < NM) {
            float cm = Cc[tid], sm = Ssv[tid];
            float ci = 1.0f / cm;
            float rm = sm * cm + MU_C;
            cinv_[tid] = ci;
            r_[tid]    = rm;
            sc_[tid]   = sm / cm;
            cinr_[tid] = ci * rm;
        }
        for (int e = tid; e < 144; e += 128) {
            int i = e / 12, j = e - 12 * i;
            float a = 0.0f, w = 0.0f;
            #pragma unroll
            for (int k = 0; k < NS; k++) {
                a += Fx[k * 12 + i] * sVxx[k * 12 + j];
                w += sVx[k] * Fxx[k * 144 + e];
            }
            fxV[e] = a; Wxx[e] = w;
        }
        for (int e = tid; e < 48; e += 128) {
            int u = e / 12, j = e - 12 * u;
            float a = 0.0f, w = 0.0f;
            #pragma unroll
            for (int k = 0; k < NS; k++) {
                a += Fu[k * 4 + u] * sVxx[k * 12 + j];
                w += sVx[k] * Fxu[k * 48 + e];          // Wxu index e = i*4+u layout reused
            }
            fuV[e] = a;
            Wxu[e] = w;   // NOTE: Wxu is stored in [i*4+u] layout via direct e on Fxu
        }
        // fix: Wxu must use e as [i*4+u]; recompute cleanly (cheap, overwrite)
        for (int e = tid; e < 48; e += 128) {
            float w = 0.0f;
            #pragma unroll
            for (int k = 0; k < NS; k++) w += sVx[k] * Fxu[k * 48 + e];
            Wxu[e] = w;
        }
        for (int e = tid; e < 16; e += 128) {
            float w = 0.0f;
            #pragma unroll
            for (int k = 0; k < NS; k++) w += sVx[k] * Fuu[k * 16 + e];
            Wuu[e] = w;
        }
        if (tid >= 32 && tid < 44) {
            int i = tid - 32;
            float a = Qxi[i];
            #pragma unroll
            for (int m = 0; m < NM; m++) a += Cx[m * 12 + i] * Ssv[m];
            #pragma unroll
            for (int k = 0; k < NS; k++) a += Fx[k * 12 + i] * sVx[k];
            QxB[i] = a;
        }
        if (tid >= 44 && tid < 48) {
            int u = tid - 44;
            float a = Qui[u];
            #pragma unroll
            for (int m = 0; m < NM; m++) a += Cu[m * 4 + u] * Ssv[m];
            #pragma unroll
            for (int k = 0; k < NS; k++) a += Fu[k * 4 + u] * sVx[k];
            QuB[u] = a;
        }
        __syncthreads();                    // S1

        // ================= Phase 2 =================
        for (int e = tid; e < 144; e += 128) {
            int i = e / 12, j = e - 12 * i;
            float a = Qxi2[e] + Wxx[e];
            #pragma unroll
            for (int k = 0; k < NS; k++) a += fxV[i * 12 + k] * Fx[k * 12 + j];
            #pragma unroll
            for (int m = 0; m < NM; m++) a -= Cx[m * 12 + i] * (sc_[m] * Cx[m * 12 + j]);
            Qxx2[e] = a;
        }
        for (int e = tid; e < 48; e += 128) {
            int u = e / 12, x = e - 12 * u;
            float a = Qxui[x * 4 + u] + Wxu[x * 4 + u];
            #pragma unroll
            for (int k = 0; k < NS; k++) a += fxV[x * 12 + k] * Fu[k * 4 + u];
            #pragma unroll
            for (int m = 0; m < NM; m++) a -= Cu[m * 4 + u] * (sc_[m] * Cx[m * 12 + x]);
            tQux[e] = a;
        }
        if (tid < 16) {
            int u = tid / 4, w = tid - 4 * u;
            float a = Quui[u * 4 + w] + Wuu[u * 4 + w];
            float b2 = Quui[w * 4 + u] + Wuu[w * 4 + u];
            #pragma unroll
            for (int k = 0; k < NS; k++) {
                a  += fuV[u * 12 + k] * Fu[k * 4 + w];
                b2 += fuV[w * 12 + k] * Fu[k * 4 + u];
            }
            float sym = 0.5f * (a + b2);
            float csc = 0.0f;
            #pragma unroll
            for (int m = 0; m < NM; m++) csc += Cu[m * 4 + u] * (sc_[m] * Cu[m * 4 + w]);
            float q2 = sym - csc;
            Quu2[tid] = q2;
            Amat[tid] = q2 + Quui[u * 4 + w] * REG_FAC;
        }
        if (tid >= 16 && tid < 28) {
            int i = tid - 16;
            float a = QxB[i];
            #pragma unroll
            for (int m = 0; m < NM; m++) a -= Cx[m * 12 + i] * cinr_[m];
            Qx2[i] = a;
        }
        if (tid >= 28 && tid < 32) {
            int u = tid - 28;
            float a = QuB[u];
            #pragma unroll
            for (int m = 0; m < NM; m++) a -= Cu[m * 4 + u] * cinr_[m];
            Quh[u] = a;
        }
        __syncthreads();                    // S2

        // ================= Phase 3: 4x4 LU solve, 13 RHS (warp 0) =================
        if (tid < 32) {
            if (tid == 0) {
                float Al[4][4];
                #pragma unroll
                for (int i = 0; i < 4; i++)
                    #pragma unroll
                    for (int j = 0; j < 4; j++) Al[i][j] = Amat[i * 4 + j];
                int pm[4] = {0, 1, 2, 3};
                #pragma unroll
                for (int k = 0; k < 4; k++) {
                    int p = k; float best = fabsf(Al[k][k]);
                    for (int rr = k + 1; rr < 4; rr++) {
                        float v = fabsf(Al[rr][k]);
                        if (v > best) { best = v; p = rr; }
                    }
                    if (p != k) {
                        #pragma unroll
                        for (int cc = 0; cc < 4; cc++) {
                            float tmp = Al[k][cc]; Al[k][cc] = Al[p][cc]; Al[p][cc] = tmp;
                        }
                        int tpi = pm[k]; pm[k] = pm[p]; pm[p] = tpi;
                    }
                    float rd = 1.0f / Al[k][k];
                    rdg[k] = rd;
                    for (int rr = k + 1; rr < 4; rr++) {
                        float ml = Al[rr][k] * rd;
                        Al[rr][k] = ml;
                        for (int cc = k + 1; cc < 4; cc++) Al[rr][cc] -= ml * Al[k][cc];
                    }
                }
                #pragma unroll
                for (int i = 0; i < 4; i++) {
                    perm[i] = pm[i];
                    #pragma unroll
                    for (int j = 0; j < 4; j++) LUm[i * 4 + j] = Al[i][j];
                }
            }
            __syncwarp();
            if (tid < 13) {
                int col = tid;
                float bv[4];
                #pragma unroll
                for (int u = 0; u < 4; u++)
                    bv[u] = (col == 0) ? Quh[u] : tQux[u * 12 + (col - 1)];
                float y[4];
                #pragma unroll
                for (int k = 0; k < 4; k++) {
                    float a = bv[perm[k]];
                    for (int j = 0; j < k; j++) a -= LUm[k * 4 + j] * y[j];
                    y[k] = a;
                }
                float x[4];
                #pragma unroll
                for (int k = 3; k >= 0; k--) {
                    float a = y[k];
                    for (int j = k + 1; j < 4; j++) a -= LUm[k * 4 + j] * x[j];
                    x[k] = a * rdg[k];
                }
                #pragma unroll
                for (int u = 0; u < 4; u++) kK[u * 13 + col] = -x[u];
            }
        }
        __syncthreads();                    // S3

        // ================= Phase 4: gains, outputs, Vx_new =================
        const int ot = b * NT + t;
        if (tid < 4) out[O_ku + (size_t)ot * 4 + tid] = kK[tid * 13];
        for (int e = tid; e < 48; e += 128) {
            int u = e / 12, x = e - 12 * u;
            out[O_Ku + (size_t)ot * 48 + e] = kK[u * 13 + 1 + x];
        }
        if (tid >= 4 && tid < 10) {
            int m = tid - 4;
            float cuku = 0.0f;
            #pragma unroll
            for (int u = 0; u < 4; u++) cuku += Cu[m * 4 + u] * kK[u * 13];
            out[O_ks + (size_t)ot * 6 + m] = -cinv_[m] * (r_[m] + Ssv[m] * cuku);
        }
        for (int e = tid; e < 72; e += 128) {
            int m = e / 12, x = e - 12 * m;
            float a = Cx[m * 12 + x];
            #pragma unroll
            for (int u = 0; u < 4; u++) a += Cu[m * 4 + u] * kK[u * 13 + 1 + x];
            out[O_Ks + (size_t)ot * 72 + e] = -sc_[m] * a;
        }
        for (int e = tid; e < 144; e += 128) {
            int x = e / 12, j = e - 12 * x;
            float a = 0.0f;
            #pragma unroll
            for (int u = 0; u < 4; u++) a += tQux[u * 12 + x] * kK[u * 13 + 1 + j];
            QxuKu[e] = a;
        }
        for (int e = tid; e < 48; e += 128) {
            int x = e / 4, u = e - 4 * x;
            float a = 0.0f;
            #pragma unroll
            for (int w = 0; w < 4; w++) a += kK[w * 13 + 1 + x] * Quu2[w * 4 + u];
            KtQ[e] = a;
        }
        if (tid >= 64 && tid < 76) {
            int x = tid - 64;
            float a = Qx2[x];
            #pragma unroll
            for (int u = 0; u < 4; u++) a += kK[u * 13 + 1 + x] * Quh[u];
            #pragma unroll
            for (int u = 0; u < 4; u++) {
                float kq = 0.0f;
                #pragma unroll
                for (int w = 0; w < 4; w++) kq += kK[w * 13 + 1 + x] * Quu2[w * 4 + u];
                a += kq * kK[u * 13];
            }
            #pragma unroll
            for (int u = 0; u < 4; u++) a += tQux[u * 12 + x] * kK[u * 13];
            VxT[x] = a;
        }
        if (tid == 96) {
            float a = 0.0f;
            #pragma unroll
            for (int u = 0; u < 4; u++) a += kK[u * 13] * Quh[u];
            sdv0 += a;
        }
        if (tid == 97) {
            float a = 0.0f;
            #pragma unroll
            for (int u = 0; u < 4; u++)
                #pragma unroll
                for (int w = 0; w < 4; w++) a += kK[u * 13] * Quu2[u * 4 + w] * kK[w * 13];
            sdv1 += 0.5f * a;
        }
        if (tid == 98) {
            float a = serrq;
            #pragma unroll
            for (int u = 0; u < 4; u++) a = fmaxf(a, fabsf(Quh[u]));
            serrq = a;
        }
        if (tid == 99) {
            float a = serrm;
            #pragma unroll
            for (int m = 0; m < NM; m++) a = fmaxf(a, fabsf(r_[m]));
            serrm = a;
        }
        __syncthreads();                    // S4

        // ================= Phase 5: Vxx_new (symmetrized) + Vx carry =================
        for (int e = tid; e < 78; e += 128) {
            int i = 0, rem = e;
            while (rem >= 12 - i) { rem -= 12 - i; i++; }
            int j = i + rem;
            float rij = Qxx2[i * 12 + j] + QxuKu[j * 12 + i] + QxuKu[i * 12 + j];
            #pragma unroll
            for (int u = 0; u < 4; u++) rij += KtQ[i * 4 + u] * kK[u * 13 + 1 + j];
            float rji = Qxx2[j * 12 + i] + QxuKu[i * 12 + j] + QxuKu[j * 12 + i];
            #pragma unroll
            for (int u = 0; u < 4; u++) rji += KtQ[j * 4 + u] * kK[u * 13 + 1 + i];
            float v = 0.5f * (rij + rji);
            sVxx[i * 12 + j] = v;
            sVxx[j * 12 + i] = v;
        }
        if (tid >= 96 && tid < 108) sVx[tid - 96] = VxT[tid - 96];

        buf ^= 1;
        // S0 of next iteration orders Phase-5 writes before reuse
    }

    __syncthreads();
    // ---- epilogue: dV, Vx, Vxx, opterr ----
    if (tid == 0) { out[O_dV + b * 2] = sdv0; out[O_dV + b * 2 + 1] = sdv1; }
    if (tid < NS) out[O_Vx + b * NS + tid] = sVx[tid];
    for (int e = tid; e < 144; e += 128) out[O_Vxx + b * 144 + e] = sVxx[e];
    if (tid == 1) {
        float e2 = fmaxf(serrq, serrm);
        atomicMax((int*)(out + O_opt), __float_as_int(e2));
    }
}

extern "C" void kernel_launch(void* const* d_in, const int* in_sizes, int n_in,
                              void* d_out, int out_size) {
    float* out = (float*)d_out;
    init_opt_kernel<<<1, 1>>>(out);
    ddp_backward_kernel<<<NB, 128>>>(
        (const float*)d_in[0],  (const float*)d_in[1],
        (const float*)d_in[2],  (const float*)d_in[3],
        (const float*)d_in[4],  (const float*)d_in[5],
        (const float*)d_in[6],  (const float*)d_in[7],
        (const float*)d_in[8],  (const float*)d_in[9],
        (const float*)d_in[10], (const float*)d_in[11],
        (const float*)d_in[12], (const float*)d_in[13],
        (const float*)d_in[14], (const float*)d_in[15],
        out);
}